// round 6
// baseline (speedup 1.0000x reference)
#include <cuda_runtime.h>

#define NUM_KPT 17
#define BATCH   64
#define HWC     6912           // 96*72
#define HW4     1728           // HWC/4
#define NSEG    3              // segments per channel
#define SEG4    576            // HW4 / NSEG; 576 = 3 * 192 -> 3 exact iterations
#define NBK     (BATCH * NUM_KPT)   // 1088
#define NJOB    (NBK * NSEG)        // 3264
#define N_ELEM  7520256.0f     // 64*17*6912
#define NTHR    192

// scratch: per-(seg,b,k) partials (every slot fully written each launch -> no init needed)
__device__ float g_A[NJOB];
__device__ float g_Bv[NJOB];
__device__ float g_P[NJOB];
__device__ float g_Q[NJOB];
__device__ unsigned int g_count = 0;   // arrival counter; reset by last block each launch

__device__ __forceinline__ float warp_sum(float v) {
    #pragma unroll
    for (int o = 16; o > 0; o >>= 1) v += __shfl_xor_sync(0xffffffffu, v, o);
    return v;
}

__global__ __launch_bounds__(NTHR, 5) void hrp_fused(
    const float* __restrict__ o11, const float* __restrict__ o12,
    const float* __restrict__ o21, const float* __restrict__ o22,
    const float* __restrict__ t1,  const float* __restrict__ t2,
    const float* __restrict__ weights, float* __restrict__ out)
{
    const int job = blockIdx.x;                // 0..3263
    const int seg = job / NBK;                 // 0..2
    const int bk  = job % NBK;                 // 0..1087 (adjacent blocks -> adjacent channels)
    const int b   = bk / NUM_KPT;
    const int k   = bk % NUM_KPT;

    const int soff = seg * SEG4;               // segment offset within channel (float4 units)
    const size_t base1 = (size_t)bk * HW4 + soff;                       // K-channel tensors
    const size_t basex = ((size_t)b * (2 * NUM_KPT) + k) * HW4 + soff;  // 2K tensors, x half
    const size_t basey = basex + (size_t)NUM_KPT * HW4;                 // y half

    const float4* O11  = (const float4*)o11 + base1;
    const float4* O21  = (const float4*)o21 + base1;
    const float4* T1   = (const float4*)t1  + base1;
    const float4* O12x = (const float4*)o12 + basex;
    const float4* O12y = (const float4*)o12 + basey;
    const float4* O22x = (const float4*)o22 + basex;
    const float4* O22y = (const float4*)o22 + basey;
    const float4* T2x  = (const float4*)t2  + basex;
    const float4* T2y  = (const float4*)t2  + basey;

    float accA = 0.f, accB = 0.f, accP = 0.f, accQ = 0.f;

    #pragma unroll 1
    for (int i = threadIdx.x; i < SEG4; i += NTHR) {
        float4 v11  = O11[i];
        float4 vt1  = T1[i];
        float4 v21  = O21[i];
        float4 v12x = O12x[i];
        float4 v12y = O12y[i];
        float4 v22x = O22x[i];
        float4 v22y = O22y[i];
        float4 vt2x = T2x[i];
        float4 vt2y = T2y[i];

        const float* p11  = &v11.x;
        const float* pt1  = &vt1.x;
        const float* p21  = &v21.x;
        const float* p12x = &v12x.x;
        const float* p12y = &v12y.x;
        const float* p22x = &v22x.x;
        const float* p22y = &v22y.x;
        const float* pt2x = &vt2x.x;
        const float* pt2y = &vt2y.x;

        #pragma unroll
        for (int l = 0; l < 4; l++) {
            float t  = pt1[l];
            float d1 = p11[l] - t;                 accA = fmaf(d1, d1, accA);
            float ex = fmaf(p12x[l], t, -pt2x[l]); accB = fmaf(ex, ex, accB);
            float ey = fmaf(p12y[l], t, -pt2y[l]); accB = fmaf(ey, ey, accB);
            float d2 = p21[l] - t;                 accP = fmaf(d2, d2, accP);
            float fx = p22x[l] - pt2x[l];
            float fy = p22y[l] - pt2y[l];
            float s  = fmaf(fx, fx, fy * fy);
            accQ = fmaf(s, t * t, accQ);
        }
    }

    // block reduce (6 warps)
    __shared__ float sA6[6], sB6[6], sP6[6], sQ6[6];
    accA = warp_sum(accA); accB = warp_sum(accB);
    accP = warp_sum(accP); accQ = warp_sum(accQ);
    const int wid = threadIdx.x >> 5, lid = threadIdx.x & 31;
    if (lid == 0) { sA6[wid] = accA; sB6[wid] = accB; sP6[wid] = accP; sQ6[wid] = accQ; }
    __syncthreads();

    __shared__ bool isLast;
    if (threadIdx.x == 0) {
        float a = 0.f, bb = 0.f, p = 0.f, q = 0.f;
        #pragma unroll
        for (int w = 0; w < 6; w++) { a += sA6[w]; bb += sB6[w]; p += sP6[w]; q += sQ6[w]; }
        g_A[job] = a; g_Bv[job] = bb; g_P[job] = p; g_Q[job] = q;
        __threadfence();                       // publish partials before arrival
        unsigned int prev = atomicAdd(&g_count, 1u);
        isLast = (prev == NJOB - 1u);
    }
    __syncthreads();
    if (!isLast) return;

    // ---- final reduction: only the last-arriving block runs this ----
    const int t = threadIdx.x;

    __shared__ float sP[NBK];   // per-(b,k) P (segments summed)
    __shared__ float sQ[NBK];   // per-(b,k) Q (segments summed)

    float a = 0.f, bb = 0.f;
    for (int i = t; i < NBK; i += NTHR) {
        sP[i] = g_P[i] + g_P[i + NBK] + g_P[i + 2 * NBK];
        sQ[i] = g_Q[i] + g_Q[i + NBK] + g_Q[i + 2 * NBK];
    }
    for (int i = t; i < NJOB; i += NTHR) {
        a  += g_A[i];
        bb += g_Bv[i];
    }
    __syncthreads();

    // rank-based top-8 per batch: fully unrolled, register+smem only,
    // matches jax.lax.top_k (largest values; lower index wins ties)
    float l21 = 0.f, l22 = 0.f;
    if (t < BATCH) {
        const float* pv = &sP[t * NUM_KPT];
        #pragma unroll
        for (int kk = 0; kk < NUM_KPT; kk++) {
            float v = pv[kk];
            int r = 0;
            #pragma unroll
            for (int j = 0; j < NUM_KPT; j++) {
                float u = pv[j];
                r += (u > v) || (u == v && j < kk);
            }
            if (r < NUM_KPT / 2) {   // r < 8 -> selected
                l21 += v;
                l22 += sQ[t * NUM_KPT + kk];
            }
        }
    }
    __syncthreads();

    // final 4-way block reduction over 192 entries (reuse sP as scratch)
    float* rA  = sP;
    float* rB  = sP + 192;
    float* r21 = sP + 384;
    float* r22 = sP + 576;
    rA[t] = a; rB[t] = bb; r21[t] = l21; r22[t] = l22;
    __syncthreads();
    // fold 192 -> 128
    if (t < 64) {
        rA[t]  += rA[t + 128];
        rB[t]  += rB[t + 128];
        r21[t] += r21[t + 128];
        r22[t] += r22[t + 128];
    }
    __syncthreads();
    #pragma unroll
    for (int s = 64; s > 0; s >>= 1) {
        if (t < s) {
            rA[t]  += rA[t + s];
            rB[t]  += rB[t + s];
            r21[t] += r21[t + s];
            r22[t] += r22[t + s];
        }
        __syncthreads();
    }

    if (t == 0) {
        float loss1_1 = rA[0] / N_ELEM;
        float loss1_2 = rB[0] / N_ELEM;
        float loss2_1 = r21[0] / (2.0f * BATCH) / (float)(BATCH * NUM_KPT);
        float loss2_2 = r22[0] / N_ELEM;
        float w0 = weights[0], w1 = weights[1];
        out[0] = (loss1_1 + loss2_1) * w0 + (loss1_2 + 5.0f * loss2_2) * w1;
        g_count = 0;                           // reset for next graph replay
    }
}

extern "C" void kernel_launch(void* const* d_in, const int* in_sizes, int n_in,
                              void* d_out, int out_size)
{
    const float* o11 = (const float*)d_in[0];
    const float* o12 = (const float*)d_in[1];
    const float* o21 = (const float*)d_in[2];
    const float* o22 = (const float*)d_in[3];
    const float* t1  = (const float*)d_in[4];
    const float* t2  = (const float*)d_in[5];
    const float* w   = (const float*)d_in[6];
    float* out = (float*)d_out;

    hrp_fused<<<NJOB, NTHR>>>(o11, o12, o21, o22, t1, t2, w, out);
}

// round 7
// speedup vs baseline: 1.1845x; 1.1845x over previous
#include <cuda_runtime.h>

#define NUM_KPT 17
#define BATCH   64
#define HWC     6912           // 96*72
#define HW4     1728           // HWC/4
#define NBK     (BATCH * NUM_KPT)   // 1088
#define N_ELEM  7520256.0f     // 64*17*6912
#define NTHR    288            // 1728 / 288 = exactly 6 iterations, no partial
#define NWARP   (NTHR / 32)    // 9

// scratch: per-(b,k) partials (every slot fully written each launch -> no init needed)
__device__ float g_A[NBK];   // sum (out1_1 - t1)^2
__device__ float g_Bv[NBK];  // sum (o12x*t1 - t2x)^2 + (o12y*t1 - t2y)^2
__device__ float g_P[NBK];   // sum (out2_1 - t1)^2
__device__ float g_Q[NBK];   // sum ((o22x-t2x)^2 + (o22y-t2y)^2) * t1^2
__device__ unsigned int g_count = 0;   // arrival counter; reset by last block each launch

__device__ __forceinline__ float warp_sum(float v) {
    #pragma unroll
    for (int o = 16; o > 0; o >>= 1) v += __shfl_xor_sync(0xffffffffu, v, o);
    return v;
}

// release-ordered arrival: one instruction instead of MEMBAR.GPU + atomic
__device__ __forceinline__ unsigned int arrive_release(unsigned int* ctr) {
    unsigned int prev;
    asm volatile("atom.add.release.gpu.u32 %0, [%1], %2;"
                 : "=r"(prev) : "l"(ctr), "r"(1u) : "memory");
    return prev;
}

// min-blocks 3 @ 288 threads -> 75-reg budget: natural 56-reg codegen with all
// 9 float4 loads front-batched is preserved (no split, no spill).
__global__ __launch_bounds__(NTHR, 3) void hrp_fused(
    const float* __restrict__ o11, const float* __restrict__ o12,
    const float* __restrict__ o21, const float* __restrict__ o22,
    const float* __restrict__ t1,  const float* __restrict__ t2,
    const float* __restrict__ weights, float* __restrict__ out)
{
    const int bk = blockIdx.x;                 // 0..1087
    const int b  = bk / NUM_KPT;
    const int k  = bk % NUM_KPT;

    const size_t base1 = (size_t)bk * HW4;                          // K-channel tensors
    const size_t basex = ((size_t)b * (2 * NUM_KPT) + k) * HW4;     // 2K tensors, x half
    const size_t basey = basex + (size_t)NUM_KPT * HW4;             // y half

    const float4* O11  = (const float4*)o11 + base1;
    const float4* O21  = (const float4*)o21 + base1;
    const float4* T1   = (const float4*)t1  + base1;
    const float4* O12x = (const float4*)o12 + basex;
    const float4* O12y = (const float4*)o12 + basey;
    const float4* O22x = (const float4*)o22 + basex;
    const float4* O22y = (const float4*)o22 + basey;
    const float4* T2x  = (const float4*)t2  + basex;
    const float4* T2y  = (const float4*)t2  + basey;

    float accA = 0.f, accB = 0.f, accP = 0.f, accQ = 0.f;

    #pragma unroll 1
    for (int i = threadIdx.x; i < HW4; i += NTHR) {   // exactly 6 full iterations
        float4 v11  = O11[i];
        float4 vt1  = T1[i];
        float4 v21  = O21[i];
        float4 v12x = O12x[i];
        float4 v12y = O12y[i];
        float4 v22x = O22x[i];
        float4 v22y = O22y[i];
        float4 vt2x = T2x[i];
        float4 vt2y = T2y[i];

        const float* p11  = &v11.x;
        const float* pt1  = &vt1.x;
        const float* p21  = &v21.x;
        const float* p12x = &v12x.x;
        const float* p12y = &v12y.x;
        const float* p22x = &v22x.x;
        const float* p22y = &v22y.x;
        const float* pt2x = &vt2x.x;
        const float* pt2y = &vt2y.x;

        #pragma unroll
        for (int l = 0; l < 4; l++) {
            float t  = pt1[l];
            float d1 = p11[l] - t;                 accA = fmaf(d1, d1, accA);
            float ex = fmaf(p12x[l], t, -pt2x[l]); accB = fmaf(ex, ex, accB);
            float ey = fmaf(p12y[l], t, -pt2y[l]); accB = fmaf(ey, ey, accB);
            float d2 = p21[l] - t;                 accP = fmaf(d2, d2, accP);
            float fx = p22x[l] - pt2x[l];
            float fy = p22y[l] - pt2y[l];
            float s  = fmaf(fx, fx, fy * fy);
            accQ = fmaf(s, t * t, accQ);
        }
    }

    // block reduce (9 warps)
    __shared__ float sAw[NWARP], sBw[NWARP], sPw[NWARP], sQw[NWARP];
    accA = warp_sum(accA); accB = warp_sum(accB);
    accP = warp_sum(accP); accQ = warp_sum(accQ);
    const int wid = threadIdx.x >> 5, lid = threadIdx.x & 31;
    if (lid == 0) { sAw[wid] = accA; sBw[wid] = accB; sPw[wid] = accP; sQw[wid] = accQ; }
    __syncthreads();

    __shared__ bool isLast;
    if (threadIdx.x == 0) {
        float a = 0.f, bb = 0.f, p = 0.f, q = 0.f;
        #pragma unroll
        for (int w = 0; w < NWARP; w++) { a += sAw[w]; bb += sBw[w]; p += sPw[w]; q += sQw[w]; }
        g_A[bk] = a; g_Bv[bk] = bb; g_P[bk] = p; g_Q[bk] = q;
        unsigned int prev = arrive_release(&g_count);   // release: partials visible first
        isLast = (prev == NBK - 1u);
    }
    __syncthreads();
    if (!isLast) return;

    // ---- final reduction: only the last-arriving block runs this ----
    const int t = threadIdx.x;

    __shared__ float sP[NBK];   // staged per-(b,k) P
    __shared__ float sQ[NBK];   // staged per-(b,k) Q

    float a = 0.f, bb = 0.f;
    for (int i = t; i < NBK; i += NTHR) {
        sP[i] = g_P[i];
        sQ[i] = g_Q[i];
        a  += g_A[i];
        bb += g_Bv[i];
    }
    __syncthreads();

    // rank-based top-8 per batch: fully unrolled, register+smem only,
    // matches jax.lax.top_k (largest values; lower index wins ties)
    float l21 = 0.f, l22 = 0.f;
    if (t < BATCH) {
        const float* pv = &sP[t * NUM_KPT];
        #pragma unroll
        for (int kk = 0; kk < NUM_KPT; kk++) {
            float v = pv[kk];
            int r = 0;
            #pragma unroll
            for (int j = 0; j < NUM_KPT; j++) {
                float u = pv[j];
                r += (u > v) || (u == v && j < kk);
            }
            if (r < NUM_KPT / 2) {   // r < 8 -> selected
                l21 += v;
                l22 += sQ[t * NUM_KPT + kk];
            }
        }
    }

    // final block reduction: per-warp shuffles then 9 partials combined by thread 0
    a   = warp_sum(a);
    bb  = warp_sum(bb);
    l21 = warp_sum(l21);
    l22 = warp_sum(l22);
    __syncthreads();   // reuse of sAw.. after earlier use
    if (lid == 0) { sAw[wid] = a; sBw[wid] = bb; sPw[wid] = l21; sQw[wid] = l22; }
    __syncthreads();

    if (t == 0) {
        float ra = 0.f, rb = 0.f, r21 = 0.f, r22 = 0.f;
        #pragma unroll
        for (int w = 0; w < NWARP; w++) { ra += sAw[w]; rb += sBw[w]; r21 += sPw[w]; r22 += sQw[w]; }
        float loss1_1 = ra / N_ELEM;
        float loss1_2 = rb / N_ELEM;
        float loss2_1 = r21 / (2.0f * BATCH) / (float)(BATCH * NUM_KPT);
        float loss2_2 = r22 / N_ELEM;
        float w0 = weights[0], w1 = weights[1];
        out[0] = (loss1_1 + loss2_1) * w0 + (loss1_2 + 5.0f * loss2_2) * w1;
        g_count = 0;                           // reset for next graph replay
    }
}

extern "C" void kernel_launch(void* const* d_in, const int* in_sizes, int n_in,
                              void* d_out, int out_size)
{
    const float* o11 = (const float*)d_in[0];
    const float* o12 = (const float*)d_in[1];
    const float* o21 = (const float*)d_in[2];
    const float* o22 = (const float*)d_in[3];
    const float* t1  = (const float*)d_in[4];
    const float* t2  = (const float*)d_in[5];
    const float* w   = (const float*)d_in[6];
    float* out = (float*)d_out;

    hrp_fused<<<NBK, NTHR>>>(o11, o12, o21, o22, t1, t2, w, out);
}

// round 8
// speedup vs baseline: 1.1917x; 1.0061x over previous
#include <cuda_runtime.h>

#define NUM_KPT 17
#define BATCH   64
#define HWC     6912           // 96*72
#define HW4     1728           // HWC/4
#define NBK     (BATCH * NUM_KPT)   // 1088
#define N_ELEM  7520256.0f     // 64*17*6912
#define NTHR    288            // 1728 / 288 = 6 iterations -> 3 unroll-2 macro-iterations
#define NWARP   (NTHR / 32)    // 9

// scratch: per-(b,k) partials (every slot fully written each launch -> no init needed)
__device__ float g_A[NBK];
__device__ float g_Bv[NBK];
__device__ float g_P[NBK];
__device__ float g_Q[NBK];
__device__ unsigned int g_count = 0;   // arrival counter; reset by last block each launch

__device__ __forceinline__ float warp_sum(float v) {
    #pragma unroll
    for (int o = 16; o > 0; o >>= 1) v += __shfl_xor_sync(0xffffffffu, v, o);
    return v;
}

// release-ordered arrival: one instruction instead of MEMBAR.GPU + atomic
__device__ __forceinline__ unsigned int arrive_release(unsigned int* ctr) {
    unsigned int prev;
    asm volatile("atom.add.release.gpu.u32 %0, [%1], %2;"
                 : "=r"(prev) : "l"(ctr), "r"(1u) : "memory");
    return prev;
}

struct Ptrs {
    const float4 *O11, *O21, *T1, *O12x, *O12y, *O22x, *O22y, *T2x, *T2y;
};

// accumulate one float4-granule position into the 4 accumulators
__device__ __forceinline__ void accum(
    const Ptrs& p, int i,
    float& accA, float& accB, float& accP, float& accQ)
{
    float4 v11  = p.O11[i];
    float4 vt1  = p.T1[i];
    float4 v21  = p.O21[i];
    float4 v12x = p.O12x[i];
    float4 v12y = p.O12y[i];
    float4 v22x = p.O22x[i];
    float4 v22y = p.O22y[i];
    float4 vt2x = p.T2x[i];
    float4 vt2y = p.T2y[i];

    const float* p11  = &v11.x;
    const float* pt1  = &vt1.x;
    const float* p21  = &v21.x;
    const float* p12x = &v12x.x;
    const float* p12y = &v12y.x;
    const float* p22x = &v22x.x;
    const float* p22y = &v22y.x;
    const float* pt2x = &vt2x.x;
    const float* pt2y = &vt2y.x;

    #pragma unroll
    for (int l = 0; l < 4; l++) {
        float t  = pt1[l];
        float d1 = p11[l] - t;                 accA = fmaf(d1, d1, accA);
        float ex = fmaf(p12x[l], t, -pt2x[l]); accB = fmaf(ex, ex, accB);
        float ey = fmaf(p12y[l], t, -pt2y[l]); accB = fmaf(ey, ey, accB);
        float d2 = p21[l] - t;                 accP = fmaf(d2, d2, accP);
        float fx = p22x[l] - pt2x[l];
        float fy = p22y[l] - pt2y[l];
        float s  = fmaf(fx, fx, fy * fy);
        accQ = fmaf(s, t * t, accQ);
    }
}

// min-blocks 2 @ 288 threads -> 113-reg budget: two full 9xfloat4 payload sets
// (unroll-2 software pipeline, 18 batched LDG.128) fit without spill.
__global__ __launch_bounds__(NTHR, 2) void hrp_fused(
    const float* __restrict__ o11, const float* __restrict__ o12,
    const float* __restrict__ o21, const float* __restrict__ o22,
    const float* __restrict__ t1,  const float* __restrict__ t2,
    const float* __restrict__ weights, float* __restrict__ out)
{
    const int bk = blockIdx.x;                 // 0..1087
    const int b  = bk / NUM_KPT;
    const int k  = bk % NUM_KPT;

    const size_t base1 = (size_t)bk * HW4;                          // K-channel tensors
    const size_t basex = ((size_t)b * (2 * NUM_KPT) + k) * HW4;     // 2K tensors, x half
    const size_t basey = basex + (size_t)NUM_KPT * HW4;             // y half

    Ptrs p;
    p.O11  = (const float4*)o11 + base1;
    p.O21  = (const float4*)o21 + base1;
    p.T1   = (const float4*)t1  + base1;
    p.O12x = (const float4*)o12 + basex;
    p.O12y = (const float4*)o12 + basey;
    p.O22x = (const float4*)o22 + basex;
    p.O22y = (const float4*)o22 + basey;
    p.T2x  = (const float4*)t2  + basex;
    p.T2y  = (const float4*)t2  + basey;

    float accA = 0.f, accB = 0.f, accP = 0.f, accQ = 0.f;

    // 6 logical iterations = 3 macro-iterations of 2 (both payload sets batched)
    #pragma unroll 1
    for (int m = 0; m < 3; m++) {
        const int i0 = threadIdx.x + (2 * m) * NTHR;
        const int i1 = i0 + NTHR;
        accum(p, i0, accA, accB, accP, accQ);
        accum(p, i1, accA, accB, accP, accQ);
    }

    // block reduce (9 warps)
    __shared__ float sAw[NWARP], sBw[NWARP], sPw[NWARP], sQw[NWARP];
    accA = warp_sum(accA); accB = warp_sum(accB);
    accP = warp_sum(accP); accQ = warp_sum(accQ);
    const int wid = threadIdx.x >> 5, lid = threadIdx.x & 31;
    if (lid == 0) { sAw[wid] = accA; sBw[wid] = accB; sPw[wid] = accP; sQw[wid] = accQ; }
    __syncthreads();

    __shared__ bool isLast;
    if (threadIdx.x == 0) {
        float a = 0.f, bb = 0.f, pp = 0.f, q = 0.f;
        #pragma unroll
        for (int w = 0; w < NWARP; w++) { a += sAw[w]; bb += sBw[w]; pp += sPw[w]; q += sQw[w]; }
        g_A[bk] = a; g_Bv[bk] = bb; g_P[bk] = pp; g_Q[bk] = q;
        unsigned int prev = arrive_release(&g_count);   // release: partials visible first
        isLast = (prev == NBK - 1u);
    }
    __syncthreads();
    if (!isLast) return;

    // ---- final reduction: only the last-arriving block runs this ----
    const int t = threadIdx.x;

    __shared__ float sP[NBK];   // staged per-(b,k) P
    __shared__ float sQ[NBK];   // staged per-(b,k) Q

    float a = 0.f, bb = 0.f;
    for (int i = t; i < NBK; i += NTHR) {
        sP[i] = g_P[i];
        sQ[i] = g_Q[i];
        a  += g_A[i];
        bb += g_Bv[i];
    }
    __syncthreads();

    // rank-based top-8 per batch (matches jax.lax.top_k: largest, lower index on ties)
    float l21 = 0.f, l22 = 0.f;
    if (t < BATCH) {
        const float* pv = &sP[t * NUM_KPT];
        #pragma unroll
        for (int kk = 0; kk < NUM_KPT; kk++) {
            float v = pv[kk];
            int r = 0;
            #pragma unroll
            for (int j = 0; j < NUM_KPT; j++) {
                float u = pv[j];
                r += (u > v) || (u == v && j < kk);
            }
            if (r < NUM_KPT / 2) {   // r < 8 -> selected
                l21 += v;
                l22 += sQ[t * NUM_KPT + kk];
            }
        }
    }

    // final block reduction: per-warp shuffles then 9 partials combined by thread 0
    a   = warp_sum(a);
    bb  = warp_sum(bb);
    l21 = warp_sum(l21);
    l22 = warp_sum(l22);
    __syncthreads();   // safe reuse of sAw.. after earlier phase
    if (lid == 0) { sAw[wid] = a; sBw[wid] = bb; sPw[wid] = l21; sQw[wid] = l22; }
    __syncthreads();

    if (t == 0) {
        float ra = 0.f, rb = 0.f, r21 = 0.f, r22 = 0.f;
        #pragma unroll
        for (int w = 0; w < NWARP; w++) { ra += sAw[w]; rb += sBw[w]; r21 += sPw[w]; r22 += sQw[w]; }
        float loss1_1 = ra / N_ELEM;
        float loss1_2 = rb / N_ELEM;
        float loss2_1 = r21 / (2.0f * BATCH) / (float)(BATCH * NUM_KPT);
        float loss2_2 = r22 / N_ELEM;
        float w0 = weights[0], w1 = weights[1];
        out[0] = (loss1_1 + loss2_1) * w0 + (loss1_2 + 5.0f * loss2_2) * w1;
        g_count = 0;                           // reset for next graph replay
    }
}

extern "C" void kernel_launch(void* const* d_in, const int* in_sizes, int n_in,
                              void* d_out, int out_size)
{
    const float* o11 = (const float*)d_in[0];
    const float* o12 = (const float*)d_in[1];
    const float* o21 = (const float*)d_in[2];
    const float* o22 = (const float*)d_in[3];
    const float* t1  = (const float*)d_in[4];
    const float* t2  = (const float*)d_in[5];
    const float* w   = (const float*)d_in[6];
    float* out = (float*)d_out;

    hrp_fused<<<NBK, NTHR>>>(o11, o12, o21, o22, t1, t2, w, out);
}